// round 2
// baseline (speedup 1.0000x reference)
#include <cuda_runtime.h>
#include <math.h>

// Problem constants
#define BATCH   4096
#define HID     512
#define CARNUM  32
#define SEQLEN  33      // 32 vehicles + 1 main
#define TDEC    60
#define XROW    198     // 6 + 32*6

// GEMM tiling
#define BM 128
#define BN 64
#define BK 16

// ---------------- scratch (device globals; no allocation allowed) -------------
__device__ float g_h[2 * 2 * BATCH * HID];    // [parity][layer][B*H]
__device__ float g_xt[BATCH * HID];           // current embedded timestep
__device__ float g_relu[BATCH * HID];         // head hidden
__device__ float g_WT[9 * HID * HID];         // transposed weights
__device__ float g_bias[4 * HID];             // bih+bhh: enc l0, enc l1, dec l0, dec l1

struct Ptr9 { const float* p[9]; };

// ---------------- helper kernels ---------------------------------------------
__global__ void zero_kernel(float* __restrict__ p, int n) {
    for (int i = blockIdx.x * blockDim.x + threadIdx.x; i < n; i += gridDim.x * blockDim.x)
        p[i] = 0.f;
}

// WT[k][h] = W[h][k] for 9 512x512 matrices
__global__ void transpose_kernel(Ptr9 s, float* __restrict__ dst) {
    __shared__ float tile[32][33];
    int m = blockIdx.z;
    const float* src = s.p[m];
    int x0 = blockIdx.x * 32, y0 = blockIdx.y * 32;
    for (int j = threadIdx.y; j < 32; j += 8)
        tile[j][threadIdx.x] = src[(y0 + j) * HID + x0 + threadIdx.x];
    __syncthreads();
    float* d = dst + (size_t)m * HID * HID;
    for (int j = threadIdx.y; j < 32; j += 8)
        d[(size_t)(x0 + j) * HID + y0 + threadIdx.x] = tile[threadIdx.x][j];
}

__global__ void bias_kernel(const float* __restrict__ ebih, const float* __restrict__ ebhh,
                            const float* __restrict__ dbih, const float* __restrict__ dbhh,
                            float* __restrict__ out) {
    int i = blockIdx.x * blockDim.x + threadIdx.x;  // 0..2047
    if (i < 1024)       out[i] = ebih[i] + ebhh[i];
    else if (i < 2048)  out[i] = dbih[i - 1024] + dbhh[i - 1024];
}

// seq_t[b][e] = tanh(x_slice @ W^T + b)   (t<32: vehicle t, t==32: main)
__global__ void embed_kernel(const float* __restrict__ x,
                             const float* __restrict__ Wm, const float* __restrict__ bm,
                             const float* __restrict__ Wv, const float* __restrict__ bv,
                             int t, float* __restrict__ out) {
    int b = blockIdx.x;
    int e = threadIdx.x;
    const float* W; const float* bb; const float* xin;
    if (t < CARNUM) { W = Wv; bb = bv; xin = &x[b * XROW + 6 + 6 * t]; }
    else            { W = Wm; bb = bm; xin = &x[b * XROW]; }
    float s = bb[e];
#pragma unroll
    for (int j = 0; j < 6; ++j) s += xin[j] * W[e * 6 + j];
    out[b * HID + e] = tanhf(s);
}

// C[M,512] = act( A1@B1 + (A2?A2@B2:0) + bias ),  M=4096, K=512 per pair
// act: 1 = tanh, 2 = relu
__global__ __launch_bounds__(256)
void gemm_kernel(const float* __restrict__ A1, const float* __restrict__ B1,
                 const float* __restrict__ A2, const float* __restrict__ B2,
                 const float* __restrict__ bias, float* __restrict__ C, int act) {
    __shared__ float As[BK][BM];   // transposed A tile
    __shared__ float Bs[BK][BN];

    int tid = threadIdx.x;
    int tx = tid & 15;            // 0..15 -> n block of 4
    int ty = tid >> 4;            // 0..15 -> m block of 8
    int mBase = blockIdx.y * BM;
    int nBase = blockIdx.x * BN;

    float acc[8][4];
#pragma unroll
    for (int m = 0; m < 8; ++m)
#pragma unroll
        for (int n = 0; n < 4; ++n) acc[m][n] = 0.f;

    int npairs = (A2 != nullptr) ? 2 : 1;
    for (int p = 0; p < npairs; ++p) {
        const float* A  = p ? A2 : A1;
        const float* Bw = p ? B2 : B1;
        for (int k0 = 0; k0 < HID; k0 += BK) {
            // A tile: 128 rows x 16 cols, stored transposed in smem
#pragma unroll
            for (int q = 0; q < 2; ++q) {
                int i = tid * 2 + q;
                int row = i >> 2;
                int kk = (i & 3) * 4;
                float4 v = *(const float4*)&A[(size_t)(mBase + row) * HID + k0 + kk];
                As[kk + 0][row] = v.x;
                As[kk + 1][row] = v.y;
                As[kk + 2][row] = v.z;
                As[kk + 3][row] = v.w;
            }
            // B tile: 16 rows x 64 cols
            {
                int krow = tid >> 4;
                int nn = (tid & 15) * 4;
                *(float4*)&Bs[krow][nn] =
                    *(const float4*)&Bw[(size_t)(k0 + krow) * HID + nBase + nn];
            }
            __syncthreads();
#pragma unroll
            for (int k = 0; k < BK; ++k) {
                float4 a0 = *(float4*)&As[k][ty * 8];
                float4 a1 = *(float4*)&As[k][ty * 8 + 4];
                float4 b0 = *(float4*)&Bs[k][tx * 4];
                float a[8] = {a0.x, a0.y, a0.z, a0.w, a1.x, a1.y, a1.z, a1.w};
                float b[4] = {b0.x, b0.y, b0.z, b0.w};
#pragma unroll
                for (int m = 0; m < 8; ++m)
#pragma unroll
                    for (int n = 0; n < 4; ++n)
                        acc[m][n] += a[m] * b[n];
            }
            __syncthreads();
        }
    }

    // epilogue: bias + activation, vectorized store
    float bfrag[4];
#pragma unroll
    for (int n = 0; n < 4; ++n) bfrag[n] = bias[nBase + tx * 4 + n];
#pragma unroll
    for (int m = 0; m < 8; ++m) {
        int gm = mBase + ty * 8 + m;
        float4 outv;
        float* o = (float*)&outv;
#pragma unroll
        for (int n = 0; n < 4; ++n) {
            float v = acc[m][n] + bfrag[n];
            if (act == 1)      v = tanhf(v);
            else if (act == 2) v = fmaxf(v, 0.f);
            o[n] = v;
        }
        *(float4*)&C[(size_t)gm * HID + nBase + tx * 4] = outv;
    }
}

// out[b, t, :] = tanh(r[b] @ W2^T + b2)  — one warp per batch row
__global__ void head2_kernel(const float* __restrict__ r, const float* __restrict__ W2,
                             const float* __restrict__ b2, float* __restrict__ out, int t) {
    int warp = (blockIdx.x * blockDim.x + threadIdx.x) >> 5;
    int lane = threadIdx.x & 31;
    if (warp >= BATCH) return;
    const float* rr = &r[(size_t)warp * HID];
    float s0 = 0.f, s1 = 0.f;
#pragma unroll
    for (int k = lane; k < HID; k += 32) {
        float v = rr[k];
        s0 += v * W2[k];
        s1 += v * W2[HID + k];
    }
#pragma unroll
    for (int off = 16; off; off >>= 1) {
        s0 += __shfl_down_sync(0xffffffffu, s0, off);
        s1 += __shfl_down_sync(0xffffffffu, s1, off);
    }
    if (lane == 0) {
        out[(size_t)warp * (TDEC * 2) + t * 2 + 0] = tanhf(s0 + b2[0]);
        out[(size_t)warp * (TDEC * 2) + t * 2 + 1] = tanhf(s1 + b2[1]);
    }
}

// ---------------- launch ------------------------------------------------------
extern "C" void kernel_launch(void* const* d_in, const int* in_sizes, int n_in,
                              void* d_out, int out_size) {
    (void)in_sizes; (void)n_in; (void)out_size;
    const float* x       = (const float*)d_in[0];
    const float* emW     = (const float*)d_in[1];
    const float* emb     = (const float*)d_in[2];
    const float* evW     = (const float*)d_in[3];
    const float* evb     = (const float*)d_in[4];
    const float* encWih  = (const float*)d_in[5];
    const float* encWhh  = (const float*)d_in[6];
    const float* encbih  = (const float*)d_in[7];
    const float* encbhh  = (const float*)d_in[8];
    const float* decWih  = (const float*)d_in[9];
    const float* decWhh  = (const float*)d_in[10];
    const float* decbih  = (const float*)d_in[11];
    const float* decbhh  = (const float*)d_in[12];
    const float* headW1  = (const float*)d_in[13];
    const float* headb1  = (const float*)d_in[14];
    const float* headW2  = (const float*)d_in[15];
    const float* headb2  = (const float*)d_in[16];
    float* out = (float*)d_out;

    float *hbuf, *xt, *relu, *wt, *bias;
    cudaGetSymbolAddress((void**)&hbuf, g_h);
    cudaGetSymbolAddress((void**)&xt,   g_xt);
    cudaGetSymbolAddress((void**)&relu, g_relu);
    cudaGetSymbolAddress((void**)&wt,   g_WT);
    cudaGetSymbolAddress((void**)&bias, g_bias);

    float* hP[2][2];
    for (int p = 0; p < 2; ++p)
        for (int l = 0; l < 2; ++l)
            hP[p][l] = hbuf + (size_t)(p * 2 + l) * BATCH * HID;
    float* WT[9];
    for (int m = 0; m < 9; ++m) WT[m] = wt + (size_t)m * HID * HID;

    const size_t MM = (size_t)HID * HID;
    Ptr9 src;
    src.p[0] = encWih;            // enc Wih l0
    src.p[1] = encWhh;            // enc Whh l0
    src.p[2] = encWih + MM;       // enc Wih l1
    src.p[3] = encWhh + MM;       // enc Whh l1
    src.p[4] = decWih;
    src.p[5] = decWhh;
    src.p[6] = decWih + MM;
    src.p[7] = decWhh + MM;
    src.p[8] = headW1;

    // init: zero parity-0 hidden state, prep transposed weights + summed biases
    zero_kernel<<<512, 256>>>(hbuf, 2 * BATCH * HID);
    transpose_kernel<<<dim3(16, 16, 9), dim3(32, 8)>>>(src, wt);
    bias_kernel<<<8, 256>>>(encbih, encbhh, decbih, decbhh, bias);

    dim3 ggrid(HID / BN, BATCH / BM);   // (8, 32)
    int s = 0;

    // ---- encoder: 33 steps ----
    for (int t = 0; t < SEQLEN; ++t) {
        int p = s & 1, q = p ^ 1;
        embed_kernel<<<BATCH, HID>>>(x, emW, emb, evW, evb, t, xt);
        // layer 0: tanh(xt@Wih0^T + h[p][0]@Whh0^T + b0)
        gemm_kernel<<<ggrid, 256>>>(xt, WT[0], hP[p][0], WT[1], bias + 0 * HID, hP[q][0], 1);
        // layer 1: tanh(h[q][0]@Wih1^T + h[p][1]@Whh1^T + b1)
        gemm_kernel<<<ggrid, 256>>>(hP[q][0], WT[2], hP[p][1], WT[3], bias + 1 * HID, hP[q][1], 1);
        s++;
    }

    // ---- decoder: 60 steps (input = previous top = h[p][1]) ----
    for (int k = 0; k < TDEC; ++k) {
        int p = s & 1, q = p ^ 1;
        gemm_kernel<<<ggrid, 256>>>(hP[p][1], WT[4], hP[p][0], WT[5], bias + 2 * HID, hP[q][0], 1);
        gemm_kernel<<<ggrid, 256>>>(hP[q][0], WT[6], hP[p][1], WT[7], bias + 3 * HID, hP[q][1], 1);
        // head hidden: relu(top@W1^T + b1)
        gemm_kernel<<<ggrid, 256>>>(hP[q][1], WT[8], nullptr, nullptr, headb1, relu, 2);
        head2_kernel<<<512, 256>>>(relu, headW2, headb2, out, k);
        s++;
    }
}

// round 3
// speedup vs baseline: 2.1119x; 2.1119x over previous
#include <cuda_runtime.h>
#include <cuda_bf16.h>
#include <math.h>

// Problem constants
#define BATCH   4096
#define HID     512
#define CARNUM  32
#define SEQLEN  33
#define TDEC    60
#define XROW    198
#define BH      (BATCH * HID)
#define MM      (HID * HID)

// GEMM tiling
#define BM 128
#define BN 64
#define BK 32
// smem strides (in bf16 halves): BK + 8 pad -> conflict-free fragment loads
#define SROW 40
// per-stage byte layout
#define OFF_AL 10240
#define OFF_BH 20480
#define OFF_BL 25600
#define STAGE  30720
#define SMEM_TOTAL (2 * STAGE)

// ---------------- device globals (no allocation allowed) ----------------------
__device__ __nv_bfloat16 g_Hh[2 * 2 * BH];            // hidden hi [parity][layer][BH]
__device__ __nv_bfloat16 g_Hl[2 * 2 * BH];            // hidden lo
__device__ __nv_bfloat16 g_Sh[SEQLEN * BH];           // embedded seq hi
__device__ __nv_bfloat16 g_Sl[SEQLEN * BH];           // embedded seq lo
__device__ __nv_bfloat16 g_Rh[BH];                    // relu hi
__device__ __nv_bfloat16 g_Rl[BH];                    // relu lo
__device__ __nv_bfloat16 g_Wh[9 * MM];                // weight hi (original [n][k] layout)
__device__ __nv_bfloat16 g_Wl[9 * MM];                // weight lo
__device__ float g_bias[4 * HID];

struct Ptr9 { const float* p[9]; };

// ---------------- helpers -----------------------------------------------------
__device__ __forceinline__ void split_bf(float v, __nv_bfloat16& h, __nv_bfloat16& l) {
    h = __float2bfloat16(v);
    l = __float2bfloat16(v - __bfloat162float(h));
}

__device__ __forceinline__ void cp16(unsigned dst, const void* src) {
    asm volatile("cp.async.cg.shared.global [%0], [%1], 16;" :: "r"(dst), "l"(src) : "memory");
}

__device__ __forceinline__ void mma16816(float* c, const unsigned* a, const unsigned* b) {
    asm volatile(
        "mma.sync.aligned.m16n8k16.row.col.f32.bf16.bf16.f32 "
        "{%0,%1,%2,%3}, {%4,%5,%6,%7}, {%8,%9}, {%0,%1,%2,%3};"
        : "+f"(c[0]), "+f"(c[1]), "+f"(c[2]), "+f"(c[3])
        : "r"(a[0]), "r"(a[1]), "r"(a[2]), "r"(a[3]), "r"(b[0]), "r"(b[1]));
}

// ---------------- prep kernels ------------------------------------------------
__global__ void wsplit_kernel(Ptr9 s, __nv_bfloat16* __restrict__ Wh,
                              __nv_bfloat16* __restrict__ Wl) {
    int m = blockIdx.y;
    int i = blockIdx.x * blockDim.x + threadIdx.x;   // 0..MM-1
    float v = s.p[m][i];
    __nv_bfloat16 h, l;
    split_bf(v, h, l);
    Wh[(size_t)m * MM + i] = h;
    Wl[(size_t)m * MM + i] = l;
}

__global__ void bias_kernel(const float* __restrict__ ebih, const float* __restrict__ ebhh,
                            const float* __restrict__ dbih, const float* __restrict__ dbhh,
                            float* __restrict__ out) {
    int i = blockIdx.x * blockDim.x + threadIdx.x;
    if (i < 1024)      out[i] = ebih[i] + ebhh[i];
    else if (i < 2048) out[i] = dbih[i - 1024] + dbhh[i - 1024];
}

__global__ void zeroh_kernel(__nv_bfloat16* __restrict__ a, __nv_bfloat16* __restrict__ b, int n) {
    int i = blockIdx.x * blockDim.x + threadIdx.x;
    if (i < n) { a[i] = __float2bfloat16(0.f); b[i] = __float2bfloat16(0.f); }
}

// all 33 embedded timesteps at once
__global__ void embed_all_kernel(const float* __restrict__ x,
                                 const float* __restrict__ Wm, const float* __restrict__ bm,
                                 const float* __restrict__ Wv, const float* __restrict__ bv,
                                 __nv_bfloat16* __restrict__ Sh, __nv_bfloat16* __restrict__ Sl) {
    int b = blockIdx.x;
    int t = blockIdx.y;
    int e = threadIdx.x;
    const float* W; const float* bb; const float* xin;
    if (t < CARNUM) { W = Wv; bb = bv; xin = &x[b * XROW + 6 + 6 * t]; }
    else            { W = Wm; bb = bm; xin = &x[b * XROW]; }
    float s = bb[e];
#pragma unroll
    for (int j = 0; j < 6; ++j) s += xin[j] * W[e * 6 + j];
    float v = tanhf(s);
    size_t idx = ((size_t)t * BATCH + b) * HID + e;
    __nv_bfloat16 h, l;
    split_bf(v, h, l);
    Sh[idx] = h; Sl[idx] = l;
}

// ---------------- bf16x3 split-precision GEMM ---------------------------------
// C[M,512] = act( sum_pairs A@B + bias ), A row-major [m][k], B col-major = W[n][k]
// act: 1 = tanh, 2 = relu.  Output written as bf16 hi/lo pair.
__global__ void __launch_bounds__(256, 2)
gemm_bf16x3(const __nv_bfloat16* __restrict__ A1h, const __nv_bfloat16* __restrict__ A1l,
            const __nv_bfloat16* __restrict__ A2h, const __nv_bfloat16* __restrict__ A2l,
            const __nv_bfloat16* __restrict__ B1h, const __nv_bfloat16* __restrict__ B1l,
            const __nv_bfloat16* __restrict__ B2h, const __nv_bfloat16* __restrict__ B2l,
            const float* __restrict__ bias,
            __nv_bfloat16* __restrict__ Ch, __nv_bfloat16* __restrict__ Cl,
            int act, int npairs) {
    extern __shared__ char smc[];
    unsigned smBase = (unsigned)__cvta_generic_to_shared(smc);

    int tid  = threadIdx.x;
    int warp = tid >> 5;
    int lane = tid & 31;
    int wm = warp & 3;          // 0..3 -> M
    int wn = warp >> 2;         // 0..1 -> N
    int g   = lane >> 2;        // 0..7
    int tig = lane & 3;         // 0..3
    int mBase = blockIdx.y * BM;
    int nBase = blockIdx.x * BN;

    float acc[2][4][4];
#pragma unroll
    for (int mt = 0; mt < 2; ++mt)
#pragma unroll
        for (int nt = 0; nt < 4; ++nt)
#pragma unroll
            for (int c = 0; c < 4; ++c) acc[mt][nt][c] = 0.f;

    int NT = npairs * (HID / BK);    // 16 or 32 tiles

    // ---- prefetch of tile it into buffer buf ----
    auto prefetch = [&](int it, int buf) {
        int pair = it >> 4;
        int k0 = (it & 15) * BK;
        const __nv_bfloat16* Agh = pair ? A2h : A1h;
        const __nv_bfloat16* Agl = pair ? A2l : A1l;
        const __nv_bfloat16* Bgh = pair ? B2h : B1h;
        const __nv_bfloat16* Bgl = pair ? B2l : B1l;
        unsigned sb = smBase + buf * STAGE;
#pragma unroll
        for (int i = 0; i < 4; ++i) {       // A: hi+lo, 128 rows x 64B
            int cid = tid + 256 * i;
            int arr = cid >> 9, r = (cid >> 2) & 127, seg = cid & 3;
            const __nv_bfloat16* s = (arr ? Agl : Agh) + (size_t)(mBase + r) * HID + k0 + seg * 8;
            cp16(sb + arr * OFF_AL + r * 80 + seg * 16, s);
        }
#pragma unroll
        for (int i = 0; i < 2; ++i) {       // B: hi+lo, 64 rows x 64B
            int cid = tid + 256 * i;
            int arr = cid >> 8, r = (cid >> 2) & 63, seg = cid & 3;
            const __nv_bfloat16* s = (arr ? Bgl : Bgh) + (size_t)(nBase + r) * HID + k0 + seg * 8;
            cp16(sb + OFF_BH + arr * 5120 + r * 80 + seg * 16, s);
        }
        asm volatile("cp.async.commit_group;" ::: "memory");
    };

    prefetch(0, 0);

    for (int it = 0; it < NT; ++it) {
        if (it + 1 < NT) {
            prefetch(it + 1, (it + 1) & 1);
            asm volatile("cp.async.wait_group 1;" ::: "memory");
        } else {
            asm volatile("cp.async.wait_group 0;" ::: "memory");
        }
        __syncthreads();

        int buf = it & 1;
        const unsigned* pAh = (const unsigned*)(smc + buf * STAGE);
        const unsigned* pAl = pAh + OFF_AL / 4;
        const unsigned* pBh = pAh + OFF_BH / 4;
        const unsigned* pBl = pAh + OFF_BL / 4;

#pragma unroll
        for (int kk = 0; kk < 2; ++kk) {
            int kb = kk * 8;
            unsigned ah[2][4], al2[2][4];
#pragma unroll
            for (int mt = 0; mt < 2; ++mt) {
                int mb = wm * 32 + mt * 16;
                int i0 = (mb + g) * (SROW / 2) + kb + tig;
                int i1 = i0 + 8 * (SROW / 2);
                ah[mt][0]  = pAh[i0];     ah[mt][1]  = pAh[i1];
                ah[mt][2]  = pAh[i0 + 4]; ah[mt][3]  = pAh[i1 + 4];
                al2[mt][0] = pAl[i0];     al2[mt][1] = pAl[i1];
                al2[mt][2] = pAl[i0 + 4]; al2[mt][3] = pAl[i1 + 4];
            }
            unsigned bh[4][2], bl2[4][2];
#pragma unroll
            for (int nt = 0; nt < 4; ++nt) {
                int nb = wn * 32 + nt * 8;
                int j0 = (nb + g) * (SROW / 2) + kb + tig;
                bh[nt][0]  = pBh[j0]; bh[nt][1]  = pBh[j0 + 4];
                bl2[nt][0] = pBl[j0]; bl2[nt][1] = pBl[j0 + 4];
            }
#pragma unroll
            for (int mt = 0; mt < 2; ++mt)
#pragma unroll
                for (int nt = 0; nt < 4; ++nt) {
                    mma16816(acc[mt][nt], ah[mt],  bh[nt]);   // hi*hi
                    mma16816(acc[mt][nt], ah[mt],  bl2[nt]);  // hi*lo
                    mma16816(acc[mt][nt], al2[mt], bh[nt]);   // lo*hi
                }
        }
        __syncthreads();
    }

    // ---- epilogue: bias + activation, split to bf16 hi/lo ----
#pragma unroll
    for (int mt = 0; mt < 2; ++mt) {
        int r0 = mBase + wm * 32 + mt * 16 + g;
#pragma unroll
        for (int nt = 0; nt < 4; ++nt) {
            int n0 = nBase + wn * 32 + nt * 8 + 2 * tig;
            float b0 = bias[n0], b1 = bias[n0 + 1];
#pragma unroll
            for (int half = 0; half < 2; ++half) {   // rows g, g+8
                int r = r0 + half * 8;
                float v0 = acc[mt][nt][half * 2 + 0] + b0;
                float v1 = acc[mt][nt][half * 2 + 1] + b1;
                if (act == 1) { v0 = tanhf(v0); v1 = tanhf(v1); }
                else          { v0 = fmaxf(v0, 0.f); v1 = fmaxf(v1, 0.f); }
                __nv_bfloat16 h0, l0, h1, l1;
                split_bf(v0, h0, l0); split_bf(v1, h1, l1);
                __nv_bfloat162 hh; hh.x = h0; hh.y = h1;
                __nv_bfloat162 ll; ll.x = l0; ll.y = l1;
                size_t idx = (size_t)r * HID + n0;
                *reinterpret_cast<__nv_bfloat162*>(&Ch[idx]) = hh;
                *reinterpret_cast<__nv_bfloat162*>(&Cl[idx]) = ll;
            }
        }
    }
}

// out[b, t, :] = tanh((rh+rl) @ W2^T + b2) — one warp per batch row
__global__ void head2_kernel(const __nv_bfloat16* __restrict__ rh,
                             const __nv_bfloat16* __restrict__ rl,
                             const float* __restrict__ W2,
                             const float* __restrict__ b2, float* __restrict__ out, int t) {
    int warp = (blockIdx.x * blockDim.x + threadIdx.x) >> 5;
    int lane = threadIdx.x & 31;
    if (warp >= BATCH) return;
    size_t base = (size_t)warp * HID;
    float s0 = 0.f, s1 = 0.f;
#pragma unroll
    for (int k = lane; k < HID; k += 32) {
        float v = __bfloat162float(rh[base + k]) + __bfloat162float(rl[base + k]);
        s0 += v * W2[k];
        s1 += v * W2[HID + k];
    }
#pragma unroll
    for (int off = 16; off; off >>= 1) {
        s0 += __shfl_down_sync(0xffffffffu, s0, off);
        s1 += __shfl_down_sync(0xffffffffu, s1, off);
    }
    if (lane == 0) {
        out[(size_t)warp * (TDEC * 2) + t * 2 + 0] = tanhf(s0 + b2[0]);
        out[(size_t)warp * (TDEC * 2) + t * 2 + 1] = tanhf(s1 + b2[1]);
    }
}

// ---------------- launch ------------------------------------------------------
extern "C" void kernel_launch(void* const* d_in, const int* in_sizes, int n_in,
                              void* d_out, int out_size) {
    (void)in_sizes; (void)n_in; (void)out_size;
    const float* x      = (const float*)d_in[0];
    const float* emW    = (const float*)d_in[1];
    const float* emb    = (const float*)d_in[2];
    const float* evW    = (const float*)d_in[3];
    const float* evb    = (const float*)d_in[4];
    const float* encWih = (const float*)d_in[5];
    const float* encWhh = (const float*)d_in[6];
    const float* encbih = (const float*)d_in[7];
    const float* encbhh = (const float*)d_in[8];
    const float* decWih = (const float*)d_in[9];
    const float* decWhh = (const float*)d_in[10];
    const float* decbih = (const float*)d_in[11];
    const float* decbhh = (const float*)d_in[12];
    const float* headW1 = (const float*)d_in[13];
    const float* headb1 = (const float*)d_in[14];
    const float* headW2 = (const float*)d_in[15];
    const float* headb2 = (const float*)d_in[16];
    float* out = (float*)d_out;

    __nv_bfloat16 *Hh, *Hl, *Sh, *Sl, *Rh, *Rl, *Wh, *Wl;
    float *bias;
    cudaGetSymbolAddress((void**)&Hh, g_Hh);
    cudaGetSymbolAddress((void**)&Hl, g_Hl);
    cudaGetSymbolAddress((void**)&Sh, g_Sh);
    cudaGetSymbolAddress((void**)&Sl, g_Sl);
    cudaGetSymbolAddress((void**)&Rh, g_Rh);
    cudaGetSymbolAddress((void**)&Rl, g_Rl);
    cudaGetSymbolAddress((void**)&Wh, g_Wh);
    cudaGetSymbolAddress((void**)&Wl, g_Wl);
    cudaGetSymbolAddress((void**)&bias, g_bias);

    cudaFuncSetAttribute(gemm_bf16x3, cudaFuncAttributeMaxDynamicSharedMemorySize, SMEM_TOTAL);

    Ptr9 src;
    src.p[0] = encWih;        src.p[1] = encWhh;
    src.p[2] = encWih + MM;   src.p[3] = encWhh + MM;
    src.p[4] = decWih;        src.p[5] = decWhh;
    src.p[6] = decWih + MM;   src.p[7] = decWhh + MM;
    src.p[8] = headW1;

    wsplit_kernel<<<dim3(MM / 256, 9), 256>>>(src, Wh, Wl);
    bias_kernel<<<8, 256>>>(encbih, encbhh, decbih, decbhh, bias);
    zeroh_kernel<<<(2 * BH + 255) / 256, 256>>>(Hh, Hl, 2 * BH);   // parity-0 region
    embed_all_kernel<<<dim3(BATCH, SEQLEN), HID>>>(x, emW, emb, evW, evb, Sh, Sl);

    auto hOff = [](int p, int l) { return (size_t)(p * 2 + l) * BH; };
    dim3 ggrid(HID / BN, BATCH / BM);   // (8, 32)
    int s = 0;

    // ---- encoder ----
    for (int t = 0; t < SEQLEN; ++t) {
        int p = s & 1, q = p ^ 1;
        gemm_bf16x3<<<ggrid, 256, SMEM_TOTAL>>>(
            Sh + (size_t)t * BH, Sl + (size_t)t * BH, Hh + hOff(p, 0), Hl + hOff(p, 0),
            Wh + 0 * MM, Wl + 0 * MM, Wh + 1 * MM, Wl + 1 * MM,
            bias + 0 * HID, Hh + hOff(q, 0), Hl + hOff(q, 0), 1, 2);
        gemm_bf16x3<<<ggrid, 256, SMEM_TOTAL>>>(
            Hh + hOff(q, 0), Hl + hOff(q, 0), Hh + hOff(p, 1), Hl + hOff(p, 1),
            Wh + 2 * MM, Wl + 2 * MM, Wh + 3 * MM, Wl + 3 * MM,
            bias + 1 * HID, Hh + hOff(q, 1), Hl + hOff(q, 1), 1, 2);
        s++;
    }

    // ---- decoder ----
    for (int k = 0; k < TDEC; ++k) {
        int p = s & 1, q = p ^ 1;
        gemm_bf16x3<<<ggrid, 256, SMEM_TOTAL>>>(
            Hh + hOff(p, 1), Hl + hOff(p, 1), Hh + hOff(p, 0), Hl + hOff(p, 0),
            Wh + 4 * MM, Wl + 4 * MM, Wh + 5 * MM, Wl + 5 * MM,
            bias + 2 * HID, Hh + hOff(q, 0), Hl + hOff(q, 0), 1, 2);
        gemm_bf16x3<<<ggrid, 256, SMEM_TOTAL>>>(
            Hh + hOff(q, 0), Hl + hOff(q, 0), Hh + hOff(p, 1), Hl + hOff(p, 1),
            Wh + 6 * MM, Wl + 6 * MM, Wh + 7 * MM, Wl + 7 * MM,
            bias + 3 * HID, Hh + hOff(q, 1), Hl + hOff(q, 1), 1, 2);
        gemm_bf16x3<<<ggrid, 256, SMEM_TOTAL>>>(
            Hh + hOff(q, 1), Hl + hOff(q, 1), nullptr, nullptr,
            Wh + 8 * MM, Wl + 8 * MM, nullptr, nullptr,
            headb1, Rh, Rl, 2, 1);
        head2_kernel<<<512, 256>>>(Rh, Rl, headW2, headb2, out, k);
        s++;
    }
}

// round 5
// speedup vs baseline: 2.9748x; 1.4086x over previous
#include <cuda_runtime.h>
#include <cuda_bf16.h>
#include <math.h>
#include <stdint.h>

// Problem constants
#define BATCH   4096
#define HID     512
#define CARNUM  32
#define SEQLEN  33
#define TDEC    60
#define XROW    198
#define BH      (BATCH * HID)
#define MM      (HID * HID)

// GEMM tiling: 128x128 CTA tile, BK=64 (128B rows, SW128), 8 warps (2M x 4N)
#define BM 128
#define BN 128
#define CHUNK_K 64
#define STAGES 3
#define TILE_BYTES 16384                 // 128 rows x 128B
#define STAGE_BYTES (4 * TILE_BYTES)     // Ah, Al, Bh, Bl
#define SMEM_REQ (1024 + STAGES * STAGE_BYTES)

#define SW128(o) ((o) ^ (((o) >> 3) & 0x70))

// ---------------- device globals ----------------------------------------------
__device__ __align__(128) __nv_bfloat16 g_Hh[2 * 2 * BH];
__device__ __align__(128) __nv_bfloat16 g_Hl[2 * 2 * BH];
__device__ __align__(128) __nv_bfloat16 g_Sh[SEQLEN * BH];
__device__ __align__(128) __nv_bfloat16 g_Sl[SEQLEN * BH];
__device__ __align__(128) __nv_bfloat16 g_Rh[BH];
__device__ __align__(128) __nv_bfloat16 g_Rl[BH];
__device__ __align__(128) __nv_bfloat16 g_Wh[9 * MM];
__device__ __align__(128) __nv_bfloat16 g_Wl[9 * MM];
__device__ float g_bias[4 * HID];

struct Ptr9 { const float* p[9]; };

// ---------------- helpers -----------------------------------------------------
__device__ __forceinline__ void split_bf(float v, __nv_bfloat16& h, __nv_bfloat16& l) {
    h = __float2bfloat16(v);
    l = __float2bfloat16(v - __bfloat162float(h));
}

__device__ __forceinline__ void cp16(unsigned dst, const void* src) {
    asm volatile("cp.async.cg.shared.global [%0], [%1], 16;" :: "r"(dst), "l"(src) : "memory");
}

__device__ __forceinline__ void ldsm4(unsigned* r, unsigned addr) {
    asm volatile("ldmatrix.sync.aligned.m8n8.x4.shared.b16 {%0,%1,%2,%3}, [%4];"
                 : "=r"(r[0]), "=r"(r[1]), "=r"(r[2]), "=r"(r[3]) : "r"(addr));
}

__device__ __forceinline__ void mma16816(float* c, const unsigned* a, const unsigned* b) {
    asm volatile(
        "mma.sync.aligned.m16n8k16.row.col.f32.bf16.bf16.f32 "
        "{%0,%1,%2,%3}, {%4,%5,%6,%7}, {%8,%9}, {%0,%1,%2,%3};"
        : "+f"(c[0]), "+f"(c[1]), "+f"(c[2]), "+f"(c[3])
        : "r"(a[0]), "r"(a[1]), "r"(a[2]), "r"(a[3]), "r"(b[0]), "r"(b[1]));
}

// ---------------- prep kernels ------------------------------------------------
__global__ void wsplit_kernel(Ptr9 s, __nv_bfloat16* __restrict__ Wh,
                              __nv_bfloat16* __restrict__ Wl) {
    int m = blockIdx.y;
    int i = blockIdx.x * blockDim.x + threadIdx.x;
    float v = s.p[m][i];
    __nv_bfloat16 h, l;
    split_bf(v, h, l);
    Wh[(size_t)m * MM + i] = h;
    Wl[(size_t)m * MM + i] = l;
}

__global__ void bias_kernel(const float* __restrict__ ebih, const float* __restrict__ ebhh,
                            const float* __restrict__ dbih, const float* __restrict__ dbhh,
                            float* __restrict__ out) {
    int i = blockIdx.x * blockDim.x + threadIdx.x;
    if (i < 1024)      out[i] = ebih[i] + ebhh[i];
    else if (i < 2048) out[i] = dbih[i - 1024] + dbhh[i - 1024];
}

__global__ void zeroh_kernel(__nv_bfloat16* __restrict__ a, __nv_bfloat16* __restrict__ b, int n) {
    int i = blockIdx.x * blockDim.x + threadIdx.x;
    if (i < n) { a[i] = __float2bfloat16(0.f); b[i] = __float2bfloat16(0.f); }
}

// one block per batch row; all 33 timesteps
__global__ void embed_all_kernel(const float* __restrict__ x,
                                 const float* __restrict__ Wm, const float* __restrict__ bm,
                                 const float* __restrict__ Wv, const float* __restrict__ bv,
                                 __nv_bfloat16* __restrict__ Sh, __nv_bfloat16* __restrict__ Sl) {
    __shared__ float sx[XROW];
    int b = blockIdx.x, e = threadIdx.x;
    if (e < XROW) sx[e] = x[(size_t)b * XROW + e];
    __syncthreads();
    float wv[6], wm[6];
#pragma unroll
    for (int j = 0; j < 6; ++j) { wv[j] = Wv[e * 6 + j]; wm[j] = Wm[e * 6 + j]; }
    float bve = bv[e], bme = bm[e];
    for (int t = 0; t < CARNUM; ++t) {
        float s = bve;
#pragma unroll
        for (int j = 0; j < 6; ++j) s += sx[6 + 6 * t + j] * wv[j];
        float v = tanhf(s);
        __nv_bfloat16 h, l; split_bf(v, h, l);
        size_t idx = ((size_t)t * BATCH + b) * HID + e;
        Sh[idx] = h; Sl[idx] = l;
    }
    {
        float s = bme;
#pragma unroll
        for (int j = 0; j < 6; ++j) s += sx[j] * wm[j];
        float v = tanhf(s);
        __nv_bfloat16 h, l; split_bf(v, h, l);
        size_t idx = ((size_t)CARNUM * BATCH + b) * HID + e;
        Sh[idx] = h; Sl[idx] = l;
    }
}

// ---------------- bf16x3 HMMA GEMM (ldmatrix + 3-stage cp.async) ---------------
// C[M,512] = act( sum_pairs A@W^T + bias ), A row-major [m][k], W [n][k]
__global__ void __launch_bounds__(256, 1)
gemm_hmma(const __nv_bfloat16* __restrict__ A1h, const __nv_bfloat16* __restrict__ A1l,
          const __nv_bfloat16* __restrict__ A2h, const __nv_bfloat16* __restrict__ A2l,
          const __nv_bfloat16* __restrict__ B1h, const __nv_bfloat16* __restrict__ B1l,
          const __nv_bfloat16* __restrict__ B2h, const __nv_bfloat16* __restrict__ B2l,
          const float* __restrict__ bias,
          __nv_bfloat16* __restrict__ Ch, __nv_bfloat16* __restrict__ Cl,
          int act, int npairs) {
    extern __shared__ char smc[];
    unsigned smraw = (unsigned)__cvta_generic_to_shared(smc);
    unsigned sm = (smraw + 1023u) & ~1023u;

    int tid  = threadIdx.x;
    int warp = tid >> 5;
    int lane = tid & 31;
    int wm = warp >> 2;        // 0..1  (M)
    int wn = warp & 3;         // 0..3  (N)
    int li  = lane & 7;
    int grp = lane >> 3;
    int mBase = blockIdx.y * BM;
    int nBase = blockIdx.x * BN;
    int NT = npairs * (HID / CHUNK_K);      // 8 or 16

    float acc[4][4][4];
#pragma unroll
    for (int mt = 0; mt < 4; ++mt)
#pragma unroll
        for (int nt = 0; nt < 4; ++nt)
#pragma unroll
            for (int c = 0; c < 4; ++c) acc[mt][nt][c] = 0.f;

    auto prefetch = [&](int chunk) {
        int buf = chunk % STAGES;
        int pair = chunk >> 3;
        int k0 = (chunk & 7) * CHUNK_K;
        const __nv_bfloat16* P0 = pair ? A2h : A1h;
        const __nv_bfloat16* P1 = pair ? A2l : A1l;
        const __nv_bfloat16* P2 = pair ? B2h : B1h;
        const __nv_bfloat16* P3 = pair ? B2l : B1l;
        unsigned sb = sm + buf * STAGE_BYTES;
#pragma unroll
        for (int i = 0; i < 16; ++i) {
            int cid = tid + 256 * i;
            int arr = cid >> 10;               // 0..3
            int r   = (cid >> 3) & 127;
            int seg = cid & 7;
            const __nv_bfloat16* p = (arr == 0) ? P0 : (arr == 1) ? P1 : (arr == 2) ? P2 : P3;
            int rb = ((arr < 2) ? mBase : nBase) + r;
            const void* src = p + (size_t)rb * HID + k0 + seg * 8;
            unsigned dst = sb + arr * TILE_BYTES + SW128(r * 128 + seg * 16);
            cp16(dst, src);
        }
        asm volatile("cp.async.commit_group;" ::: "memory");
    };

    prefetch(0);
    if (NT > 1) prefetch(1);

    for (int c = 0; c < NT; ++c) {
        if (c + 2 < NT) prefetch(c + 2);
        if (c + 2 < NT)      asm volatile("cp.async.wait_group 2;" ::: "memory");
        else if (c + 1 < NT) asm volatile("cp.async.wait_group 1;" ::: "memory");
        else                 asm volatile("cp.async.wait_group 0;" ::: "memory");
        __syncthreads();

        unsigned sb  = sm + (c % STAGES) * STAGE_BYTES;
        unsigned sAh = sb;
        unsigned sAl = sb + TILE_BYTES;
        unsigned sBh = sb + 2 * TILE_BYTES;
        unsigned sBl = sb + 3 * TILE_BYTES;

#pragma unroll
        for (int kq = 0; kq < 4; ++kq) {
            unsigned ah[4][4], al_[4][4];
#pragma unroll
            for (int mt = 0; mt < 4; ++mt) {
                int r = wm * 64 + mt * 16 + ((grp & 1) << 3) + li;
                int cc = kq * 32 + ((grp & 2) << 3);
                unsigned off = (unsigned)(r * 128 + (cc ^ (li << 4)));
                ldsm4(ah[mt],  sAh + off);
                ldsm4(al_[mt], sAl + off);
            }
            unsigned bh[2][4], bl_[2][4];
#pragma unroll
            for (int nb = 0; nb < 2; ++nb) {
                int n = wn * 32 + nb * 16 + ((grp & 2) << 2) + li;
                int cc = kq * 32 + ((grp & 1) << 4);
                unsigned off = (unsigned)(n * 128 + (cc ^ (li << 4)));
                ldsm4(bh[nb],  sBh + off);
                ldsm4(bl_[nb], sBl + off);
            }
            // term-major ordering: same-acc MMAs are 16 apart
#pragma unroll
            for (int mt = 0; mt < 4; ++mt)
#pragma unroll
                for (int nt = 0; nt < 4; ++nt)
                    mma16816(acc[mt][nt], ah[mt], &bh[nt >> 1][(nt & 1) * 2]);
#pragma unroll
            for (int mt = 0; mt < 4; ++mt)
#pragma unroll
                for (int nt = 0; nt < 4; ++nt)
                    mma16816(acc[mt][nt], ah[mt], &bl_[nt >> 1][(nt & 1) * 2]);
#pragma unroll
            for (int mt = 0; mt < 4; ++mt)
#pragma unroll
                for (int nt = 0; nt < 4; ++nt)
                    mma16816(acc[mt][nt], al_[mt], &bh[nt >> 1][(nt & 1) * 2]);
        }
        __syncthreads();
    }

    // ---- epilogue: bias + activation, split to bf16 hi/lo ----
#pragma unroll
    for (int mt = 0; mt < 4; ++mt) {
        int r0 = mBase + wm * 64 + mt * 16 + (lane >> 2);
#pragma unroll
        for (int nt = 0; nt < 4; ++nt) {
            int n0 = nBase + wn * 32 + nt * 8 + 2 * (lane & 3);
            float b0 = bias[n0], b1 = bias[n0 + 1];
#pragma unroll
            for (int half = 0; half < 2; ++half) {
                int r = r0 + half * 8;
                float v0 = acc[mt][nt][half * 2 + 0] + b0;
                float v1 = acc[mt][nt][half * 2 + 1] + b1;
                if (act == 1) { v0 = tanhf(v0); v1 = tanhf(v1); }
                else          { v0 = fmaxf(v0, 0.f); v1 = fmaxf(v1, 0.f); }
                __nv_bfloat16 h0, l0, h1, l1;
                split_bf(v0, h0, l0); split_bf(v1, h1, l1);
                __nv_bfloat162 hh; hh.x = h0; hh.y = h1;
                __nv_bfloat162 ll; ll.x = l0; ll.y = l1;
                size_t idx = (size_t)r * HID + n0;
                *reinterpret_cast<__nv_bfloat162*>(&Ch[idx]) = hh;
                *reinterpret_cast<__nv_bfloat162*>(&Cl[idx]) = ll;
            }
        }
    }
}

// out[b, t, :] = tanh((rh+rl) @ W2^T + b2)
__global__ void head2_kernel(const __nv_bfloat16* __restrict__ rh,
                             const __nv_bfloat16* __restrict__ rl,
                             const float* __restrict__ W2,
                             const float* __restrict__ b2, float* __restrict__ out, int t) {
    int warp = (blockIdx.x * blockDim.x + threadIdx.x) >> 5;
    int lane = threadIdx.x & 31;
    if (warp >= BATCH) return;
    size_t base = (size_t)warp * HID;
    float s0 = 0.f, s1 = 0.f;
#pragma unroll
    for (int k = lane; k < HID; k += 32) {
        float v = __bfloat162float(rh[base + k]) + __bfloat162float(rl[base + k]);
        s0 += v * W2[k];
        s1 += v * W2[HID + k];
    }
#pragma unroll
    for (int off = 16; off; off >>= 1) {
        s0 += __shfl_down_sync(0xffffffffu, s0, off);
        s1 += __shfl_down_sync(0xffffffffu, s1, off);
    }
    if (lane == 0) {
        out[(size_t)warp * (TDEC * 2) + t * 2 + 0] = tanhf(s0 + b2[0]);
        out[(size_t)warp * (TDEC * 2) + t * 2 + 1] = tanhf(s1 + b2[1]);
    }
}

// ---------------- launch ------------------------------------------------------
extern "C" void kernel_launch(void* const* d_in, const int* in_sizes, int n_in,
                              void* d_out, int out_size) {
    (void)in_sizes; (void)n_in; (void)out_size;
    const float* x      = (const float*)d_in[0];
    const float* emW    = (const float*)d_in[1];
    const float* emb    = (const float*)d_in[2];
    const float* evW    = (const float*)d_in[3];
    const float* evb    = (const float*)d_in[4];
    const float* encWih = (const float*)d_in[5];
    const float* encWhh = (const float*)d_in[6];
    const float* encbih = (const float*)d_in[7];
    const float* encbhh = (const float*)d_in[8];
    const float* decWih = (const float*)d_in[9];
    const float* decWhh = (const float*)d_in[10];
    const float* decbih = (const float*)d_in[11];
    const float* decbhh = (const float*)d_in[12];
    const float* headW1 = (const float*)d_in[13];
    const float* headb1 = (const float*)d_in[14];
    const float* headW2 = (const float*)d_in[15];
    const float* headb2 = (const float*)d_in[16];
    float* out = (float*)d_out;

    __nv_bfloat16 *Hh, *Hl, *Sh, *Sl, *Rh, *Rl, *Wh, *Wl;
    float *bias;
    cudaGetSymbolAddress((void**)&Hh, g_Hh);
    cudaGetSymbolAddress((void**)&Hl, g_Hl);
    cudaGetSymbolAddress((void**)&Sh, g_Sh);
    cudaGetSymbolAddress((void**)&Sl, g_Sl);
    cudaGetSymbolAddress((void**)&Rh, g_Rh);
    cudaGetSymbolAddress((void**)&Rl, g_Rl);
    cudaGetSymbolAddress((void**)&Wh, g_Wh);
    cudaGetSymbolAddress((void**)&Wl, g_Wl);
    cudaGetSymbolAddress((void**)&bias, g_bias);

    cudaFuncSetAttribute(gemm_hmma, cudaFuncAttributeMaxDynamicSharedMemorySize, SMEM_REQ);

    Ptr9 src;
    src.p[0] = encWih;        src.p[1] = encWhh;
    src.p[2] = encWih + MM;   src.p[3] = encWhh + MM;
    src.p[4] = decWih;        src.p[5] = decWhh;
    src.p[6] = decWih + MM;   src.p[7] = decWhh + MM;
    src.p[8] = headW1;

    wsplit_kernel<<<dim3(MM / 256, 9), 256>>>(src, Wh, Wl);
    bias_kernel<<<8, 256>>>(encbih, encbhh, decbih, decbhh, bias);
    zeroh_kernel<<<(2 * BH + 255) / 256, 256>>>(Hh, Hl, 2 * BH);
    embed_all_kernel<<<BATCH, HID>>>(x, emW, emb, evW, evb, Sh, Sl);

    auto hOff = [](int p, int l) { return (size_t)(p * 2 + l) * BH; };
    dim3 ggrid(HID / BN, BATCH / BM);   // (4, 32) = 128 CTAs
    int s = 0;

    // ---- encoder ----
    for (int t = 0; t < SEQLEN; ++t) {
        int p = s & 1, q = p ^ 1;
        gemm_hmma<<<ggrid, 256, SMEM_REQ>>>(
            Sh + (size_t)t * BH, Sl + (size_t)t * BH, Hh + hOff(p, 0), Hl + hOff(p, 0),
            Wh + 0 * MM, Wl + 0 * MM, Wh + 1 * MM, Wl + 1 * MM,
            bias + 0 * HID, Hh + hOff(q, 0), Hl + hOff(q, 0), 1, 2);
        gemm_hmma<<<ggrid, 256, SMEM_REQ>>>(
            Hh + hOff(q, 0), Hl + hOff(q, 0), Hh + hOff(p, 1), Hl + hOff(p, 1),
            Wh + 2 * MM, Wl + 2 * MM, Wh + 3 * MM, Wl + 3 * MM,
            bias + 1 * HID, Hh + hOff(q, 1), Hl + hOff(q, 1), 1, 2);
        s++;
    }

    // ---- decoder ----
    for (int k = 0; k < TDEC; ++k) {
        int p = s & 1, q = p ^ 1;
        gemm_hmma<<<ggrid, 256, SMEM_REQ>>>(
            Hh + hOff(p, 1), Hl + hOff(p, 1), Hh + hOff(p, 0), Hl + hOff(p, 0),
            Wh + 4 * MM, Wl + 4 * MM, Wh + 5 * MM, Wl + 5 * MM,
            bias + 2 * HID, Hh + hOff(q, 0), Hl + hOff(q, 0), 1, 2);
        gemm_hmma<<<ggrid, 256, SMEM_REQ>>>(
            Hh + hOff(q, 0), Hl + hOff(q, 0), Hh + hOff(p, 1), Hl + hOff(p, 1),
            Wh + 6 * MM, Wl + 6 * MM, Wh + 7 * MM, Wl + 7 * MM,
            bias + 3 * HID, Hh + hOff(q, 1), Hl + hOff(q, 1), 1, 2);
        gemm_hmma<<<ggrid, 256, SMEM_REQ>>>(
            Hh + hOff(q, 1), Hl + hOff(q, 1), nullptr, nullptr,
            Wh + 8 * MM, Wl + 8 * MM, nullptr, nullptr,
            headb1, Rh, Rl, 2, 1);
        head2_kernel<<<512, 256>>>(Rh, Rl, headW2, headb2, out, k);
        s++;
    }
}